// round 7
// baseline (speedup 1.0000x reference)
#include <cuda_runtime.h>
#include <math.h>

#define N_NODES 20000
#define N_EDGES 400000
#define KDIM 4160
typedef unsigned long long ull;

// ---------------- device globals --------------------------------------------
__device__ float g_S[(size_t)N_NODES * KDIM];    // per-node coefficient rows
__device__ float g_B[2][KDIM * 16];              // GEMM B per layer
__device__ float g_h0[N_NODES * 16];
__device__ float g_h1[N_NODES * 16];
__device__ int   g_deg[N_NODES];                 // re-zeroed by k_fill
__device__ int   g_cursor[N_NODES];              // re-zeroed by k_scan
__device__ int   g_off[N_NODES + 1];
__device__ int2  g_es[N_EDGES];                  // (edge id, src) sorted by dst

__device__ __forceinline__ float* pick_buf(int s, float* ext) {
    if (s == 0) return g_h0;
    if (s == 1) return g_h1;
    return ext;
}

// ---------------- f32x2 helpers ----------------------------------------------
__device__ __forceinline__ ull pack2(float a, float b) {
    ull r; asm("mov.b64 %0, {%1, %2};" : "=l"(r) : "f"(a), "f"(b)); return r;
}
__device__ __forceinline__ void unpack2(ull v, float& a, float& b) {
    asm("mov.b64 {%0, %1}, %2;" : "=f"(a), "=f"(b) : "l"(v));
}
__device__ __forceinline__ ull fma2(ull a, ull b, ull c) {
    ull d; asm("fma.rn.f32x2 %0, %1, %2, %3;" : "=l"(d) : "l"(a), "l"(b), "l"(c));
    return d;
}
__device__ __forceinline__ ull add2(ull a, ull b) {
    ull d; asm("add.rn.f32x2 %0, %1, %2;" : "=l"(d) : "l"(a), "l"(b)); return d;
}

// ---------------- launch 0: degree count + node embedding --------------------
#define COUNT_BLOCKS 1563
__global__ void k_count_embed(const int* __restrict__ ei,
                              const float* __restrict__ x,
                              const float* __restrict__ Wn,
                              const float* __restrict__ bn) {
    int b = blockIdx.x;
    if (b < COUNT_BLOCKS) {
        int e = b * 256 + threadIdx.x;
        if (e < N_EDGES) atomicAdd(&g_deg[ei[N_EDGES + e]], 1);
    } else {
        __shared__ float sW[256];
        __shared__ float sb[16];
        int tid = threadIdx.x;
        sW[tid] = Wn[tid];
        if (tid < 16) sb[tid] = bn[tid];
        __syncthreads();
        int n = (b - COUNT_BLOCKS) * 256 + tid;
        if (n >= N_NODES) return;
        float xi[16];
        const float4* xp = (const float4*)(x + (size_t)n * 16);
#pragma unroll
        for (int q = 0; q < 4; q++) {
            float4 v = xp[q];
            xi[4*q] = v.x; xi[4*q+1] = v.y; xi[4*q+2] = v.z; xi[4*q+3] = v.w;
        }
        float o[16];
#pragma unroll
        for (int d = 0; d < 16; d++) {
            float acc = sb[d];
#pragma unroll
            for (int k = 0; k < 16; k++) acc = fmaf(xi[k], sW[k*16+d], acc);
            o[d] = fmaxf(acc, 0.f);
        }
        float4* op = (float4*)(g_h0 + (size_t)n * 16);
#pragma unroll
        for (int q = 0; q < 4; q++)
            op[q] = make_float4(o[4*q], o[4*q+1], o[4*q+2], o[4*q+3]);
    }
}

// ---------------- launch 1: prefix scan --------------------------------------
__global__ void __launch_bounds__(1024) k_scan() {
    __shared__ int sm[1024];
    int t = threadIdx.x;
    int base = t * 20;
    int vals[20];
    int local = 0;
#pragma unroll
    for (int i = 0; i < 20; i++) {
        int idx = base + i;
        vals[i] = (idx < N_NODES) ? g_deg[idx] : 0;
        local += vals[i];
    }
    sm[t] = local;
    __syncthreads();
    for (int off = 1; off < 1024; off <<= 1) {
        int v = (t >= off) ? sm[t - off] : 0;
        __syncthreads();
        sm[t] += v;
        __syncthreads();
    }
    int run = sm[t] - local;
#pragma unroll
    for (int i = 0; i < 20; i++) {
        int idx = base + i;
        if (idx < N_NODES) { g_off[idx] = run; run += vals[i]; g_cursor[idx] = 0; }
    }
    if (t == 0) g_off[N_NODES] = N_EDGES;
}

// ---------------- launch 2: fill sorted edge list ----------------------------
__global__ void k_fill(const int* __restrict__ ei) {
    int e = blockIdx.x * blockDim.x + threadIdx.x;
    if (e < N_EDGES) {
        int d = ei[N_EDGES + e];
        int pos = g_off[d] + atomicAdd(&g_cursor[d], 1);
        g_es[pos] = make_int2(e, ei[e]);
    }
    if (e < N_NODES) g_deg[e] = 0;
}

// ---------------- edge pass: build S rows ------------------------------------
// 2 warps per node (k-halves of 64). W1 slice + T live in registers.
__global__ void __launch_bounds__(256, 1) k_edge_pass(
    int sin, const float* __restrict__ ea,
    const float* __restrict__ W1, const float* __restrict__ b1) {
    const float* hin = (sin == 0) ? g_h0 : g_h1;
    int tid = threadIdx.x, wid = tid >> 5, l = tid & 31;
    int w = wid & 1;                 // k-half
    int n = blockIdx.x * 4 + (wid >> 1);

    // register W1 slice: w1r[c][q] = (W1[2q][k], W1[2q+1][k]), k = w*64+c*32+l
    ull w1r[2][8]; float b1r[2];
#pragma unroll
    for (int c = 0; c < 2; c++) {
        int k = w*64 + c*32 + l;
        b1r[c] = b1[k];
#pragma unroll
        for (int q = 0; q < 8; q++)
            w1r[c][q] = pack2(W1[(2*q)*128 + k], W1[(2*q+1)*128 + k]);
    }

    int start = g_off[n], end = g_off[n + 1];
    ull T[2][8];
#pragma unroll
    for (int c = 0; c < 2; c++)
#pragma unroll
        for (int q = 0; q < 8; q++) T[c][q] = 0ull;
    ull Hs[8];
#pragma unroll
    for (int q = 0; q < 8; q++) Hs[q] = 0ull;
    float Hsum[2] = {0.f, 0.f};

    for (int pos = start; pos < end; pos++) {
        int2 es = g_es[pos];
        const ulonglong2* eap = (const ulonglong2*)(ea + (size_t)es.x * 16);
        const ulonglong2* hjp = (const ulonglong2*)(hin + (size_t)es.y * 16);
        ulonglong2 e0 = eap[0], e1 = eap[1], e2 = eap[2], e3 = eap[3];
        ulonglong2 h0 = hjp[0], h1 = hjp[1], h2 = hjp[2], h3 = hjp[3];
        ull ev[8] = {e0.x, e0.y, e1.x, e1.y, e2.x, e2.y, e3.x, e3.y};
        ull hv[8] = {h0.x, h0.y, h1.x, h1.y, h2.x, h2.y, h3.x, h3.y};
        if (w == 0) {
#pragma unroll
            for (int q = 0; q < 8; q++) Hs[q] = add2(Hs[q], hv[q]);
        }
#pragma unroll
        for (int c = 0; c < 2; c++) {
            ull acc = pack2(b1r[c], 0.f);
#pragma unroll
            for (int q = 0; q < 8; q++) acc = fma2(ev[q], w1r[c][q], acc);
            float a0, a1; unpack2(acc, a0, a1);
            float hd = fmaxf(a0 + a1, 0.f);
            Hsum[c] += hd;
            ull hd2 = pack2(hd, hd);
#pragma unroll
            for (int q = 0; q < 8; q++) T[c][q] = fma2(hd2, hv[q], T[c][q]);
        }
    }

    float* Srow = g_S + (size_t)n * KDIM;
    float hn = (l < 16) ? hin[(size_t)n * 16 + l] : 0.f;
    ull hn2[8];
#pragma unroll
    for (int r = 0; r < 8; r++)
        hn2[r] = pack2(__shfl_sync(0xffffffffu, hn, 2*r),
                       __shfl_sync(0xffffffffu, hn, 2*r + 1));

#pragma unroll
    for (int c = 0; c < 2; c++) {
        int k = w*64 + c*32 + l;
        float t[16];
#pragma unroll
        for (int q = 0; q < 8; q++) unpack2(T[c][q], t[2*q], t[2*q+1]);
        float4* dT = (float4*)(Srow + (size_t)k * 16);
        dT[0] = make_float4(t[0], t[1], t[2], t[3]);
        dT[1] = make_float4(t[4], t[5], t[6], t[7]);
        dT[2] = make_float4(t[8], t[9], t[10], t[11]);
        dT[3] = make_float4(t[12], t[13], t[14], t[15]);
        ull hs2 = pack2(Hsum[c], Hsum[c]);
        float u[16];
#pragma unroll
        for (int r = 0; r < 8; r++) {
            ull v = fma2(hs2, hn2[r], 0ull);
            unpack2(v, u[2*r], u[2*r+1]);
        }
        float4* dU = (float4*)(Srow + 2048 + (size_t)k * 16);
        dU[0] = make_float4(u[0], u[1], u[2], u[3]);
        dU[1] = make_float4(u[4], u[5], u[6], u[7]);
        dU[2] = make_float4(u[8], u[9], u[10], u[11]);
        dU[3] = make_float4(u[12], u[13], u[14], u[15]);
    }

    if (w == 0) {
        float dg = (float)(end - start);
        if (l < 16) {
            Srow[4096 + l] = dg * hn;     // pairs with b2 dst rows
            Srow[4128 + l] = hn;          // pairs with root rows
            Srow[4144 + l] = 0.f;         // pad
        }
        if (l == 0) {
#pragma unroll
            for (int q = 0; q < 8; q++) {
                float a, b; unpack2(Hs[q], a, b);
                Srow[4112 + 2*q] = a;
                Srow[4112 + 2*q + 1] = b;
            }
        }
    }
}

// ---------------- build B (both layers) --------------------------------------
__global__ void k_init(const float* __restrict__ W2, const float* __restrict__ b2,
                       const float* __restrict__ root1, const float* __restrict__ root2) {
    int idx = blockIdx.x * 256 + threadIdx.x;
    if (idx >= 2 * KDIM * 16) return;
    int layer = idx / (KDIM * 16);
    int m = idx % (KDIM * 16);
    int kj = m >> 4, d = m & 15;
    const float* root = layer ? root2 : root1;
    float v = 0.f;
    if (kj < 2048) {                       // T rows
        int k = kj >> 4, j = kj & 15;
        v = W2[(size_t)k * 512 + (16 + j) * 16 + d];
    } else if (kj < 4096) {                // Hsum*h rows
        int mm = kj - 2048;
        int k = mm >> 4, r = mm & 15;
        v = W2[(size_t)k * 512 + r * 16 + d];
    } else if (kj < 4112) {                // deg*h rows
        v = b2[(kj - 4096) * 16 + d];
    } else if (kj < 4128) {                // Hs rows
        v = b2[256 + (kj - 4112) * 16 + d];
    } else if (kj < 4144) {                // h rows
        v = root[(kj - 4128) * 16 + d];
    }
    g_B[layer][kj * 16 + d] = v;
}

// ---------------- GEMM: out = S @ B + bias -----------------------------------
#define GT 256
#define SA_P 129
__global__ void __launch_bounds__(GT) k_gemm(int layer, int sout, float* ext,
                                             const float* __restrict__ bias) {
    __shared__ __align__(16) float sA[64 * SA_P];
    __shared__ __align__(16) float sB[64 * 16];
    float* hout = pick_buf(sout, ext);
    const float* B = g_B[layer];
    int tid = threadIdx.x;
    int n0 = blockIdx.x * 128;
    int nn = tid & 127, half = tid >> 7;
    ull acc[4] = {0ull, 0ull, 0ull, 0ull};

    for (int ch = 0; ch < 65; ch++) {
        int k0 = ch * 64;
        __syncthreads();
        ((float4*)sB)[tid] = ((const float4*)(B + (size_t)k0 * 16))[tid];
        for (int i = tid; i < 2048; i += GT) {
            int an = i >> 4, q = i & 15;
            float4 v = make_float4(0.f, 0.f, 0.f, 0.f);
            if (n0 + an < N_NODES)
                v = *(const float4*)(g_S + (size_t)(n0 + an) * KDIM + k0 + 4*q);
            sA[(4*q + 0) * SA_P + an] = v.x;
            sA[(4*q + 1) * SA_P + an] = v.y;
            sA[(4*q + 2) * SA_P + an] = v.z;
            sA[(4*q + 3) * SA_P + an] = v.w;
        }
        __syncthreads();
#pragma unroll 8
        for (int k = 0; k < 64; k++) {
            float a = sA[k * SA_P + nn];
            ull a2 = pack2(a, a);
            ulonglong2 b01 = *(const ulonglong2*)&sB[k * 16 + 8 * half];
            ulonglong2 b23 = *(const ulonglong2*)&sB[k * 16 + 8 * half + 4];
            acc[0] = fma2(a2, b01.x, acc[0]);
            acc[1] = fma2(a2, b01.y, acc[1]);
            acc[2] = fma2(a2, b23.x, acc[2]);
            acc[3] = fma2(a2, b23.y, acc[3]);
        }
    }

    int n = n0 + nn;
    if (n < N_NODES) {
        float o[8];
        unpack2(acc[0], o[0], o[1]);
        unpack2(acc[1], o[2], o[3]);
        unpack2(acc[2], o[4], o[5]);
        unpack2(acc[3], o[6], o[7]);
        float* dst = hout + (size_t)n * 16 + 8 * half;
#pragma unroll
        for (int j = 0; j < 8; j++) dst[j] = o[j] + bias[8 * half + j];
    }
}

// ---------------- edge embedding + log_softmax --------------------------------
__global__ void k_edge_embed(const float* __restrict__ ea,
                             const float* __restrict__ We,
                             const float* __restrict__ be,
                             float* __restrict__ ee_out,
                             float* __restrict__ lsm_out,
                             int n_ee, int n_lsm) {
    __shared__ float sW[256];
    __shared__ float sb[16];
    int tid = threadIdx.x;
    if (tid < 256) sW[tid] = We[tid];
    if (tid < 16) sb[tid] = be[tid];
    __syncthreads();
    int e = blockIdx.x * blockDim.x + tid;
    if (e >= N_EDGES) return;
    float xi[16];
    const float4* xp = (const float4*)(ea + (size_t)e * 16);
#pragma unroll
    for (int q = 0; q < 4; q++) {
        float4 v = xp[q];
        xi[4*q] = v.x; xi[4*q+1] = v.y; xi[4*q+2] = v.z; xi[4*q+3] = v.w;
    }
    float v[16];
    float m = -1e30f;
#pragma unroll
    for (int d = 0; d < 16; d++) {
        float acc = sb[d];
#pragma unroll
        for (int k = 0; k < 16; k++) acc = fmaf(xi[k], sW[k*16+d], acc);
        v[d] = fmaxf(acc, 0.f);
        m = fmaxf(m, v[d]);
    }
    float s = 0.f;
#pragma unroll
    for (int d = 0; d < 16; d++) s += expf(v[d] - m);
    float ls = m + logf(s);
    if (e < n_ee) {
        float4* eo = (float4*)(ee_out + (size_t)e * 16);
#pragma unroll
        for (int q = 0; q < 4; q++)
            eo[q] = make_float4(v[4*q], v[4*q+1], v[4*q+2], v[4*q+3]);
    }
    if (e < n_lsm) {
        float4* lo = (float4*)(lsm_out + (size_t)e * 16);
#pragma unroll
        for (int q = 0; q < 4; q++)
            lo[q] = make_float4(v[4*q] - ls, v[4*q+1] - ls, v[4*q+2] - ls, v[4*q+3] - ls);
    }
}

// ---------------- edge_index passthrough --------------------------------------
__global__ void k_ei_copy(const int* __restrict__ ei, float* __restrict__ out,
                          int n_vals) {
    int i = blockIdx.x * blockDim.x + threadIdx.x;
    if (i < n_vals) out[i] = (float)ei[i];
}

// ---------------- launch -------------------------------------------------------
extern "C" void kernel_launch(void* const* d_in, const int* in_sizes, int n_in,
                              void* d_out, int out_size) {
    const float* x     = (const float*)d_in[0];
    const int*   ei    = (const int*)d_in[1];
    const float* ea    = (const float*)d_in[2];
    const float* Wn    = (const float*)d_in[3];
    const float* bn    = (const float*)d_in[4];
    const float* We    = (const float*)d_in[5];
    const float* be    = (const float*)d_in[6];
    const float* W1    = (const float*)d_in[7];
    const float* b1    = (const float*)d_in[8];
    const float* W2    = (const float*)d_in[9];
    const float* b2    = (const float*)d_in[10];
    const float* root1 = (const float*)d_in[11];
    const float* bias1 = (const float*)d_in[12];
    const float* root2 = (const float*)d_in[13];
    const float* bias2 = (const float*)d_in[14];

    float* out = (float*)d_out;
    size_t cap = (size_t)out_size;

    size_t ei_slots = (cap == 13120000) ? 0 : 2ull * N_EDGES;
    size_t off_h   = 0;
    size_t off_ei  = off_h + (size_t)N_NODES * 16;
    size_t off_ee  = off_ei + ei_slots;
    size_t off_lsm = off_ee + (size_t)N_EDGES * 16;
    auto avail = [&](size_t off) -> size_t { return off < cap ? cap - off : 0; };

    float* out_h   = out + off_h;
    float* out_ei  = out + off_ei;
    float* out_ee  = out + off_ee;
    float* out_lsm = out + off_lsm;

    bool h_fits = avail(off_h) >= (size_t)N_NODES * 16;
    int  n_ei   = ei_slots ? (int)min((size_t)(2 * N_EDGES), avail(off_ei)) : 0;
    int  n_ee   = (int)min((size_t)N_EDGES, avail(off_ee) / 16);
    int  n_lsm  = (int)min((size_t)N_EDGES, avail(off_lsm) / 16);

    // 0: degree count + node embedding (g_deg zeroed by prior run / loader)
    k_count_embed<<<COUNT_BLOCKS + 79, 256>>>(ei, x, Wn, bn);
    // 1: prefix scan (re-zeros g_cursor)
    k_scan<<<1, 1024>>>();
    // 2: dst-sorted edge list (re-zeros g_deg)
    k_fill<<<COUNT_BLOCKS, 256>>>(ei);

    // 3: edge pass layer 1 (profiled by ncu -s)
    k_edge_pass<<<N_NODES / 4, 256>>>(0, ea, W1, b1);
    // 4: build B (both layers)
    k_init<<<(2 * KDIM * 16 + 255) / 256, 256>>>(W2, b2, root1, root2);
    // 5: GEMM layer 1 -> g_h1
    k_gemm<<<(N_NODES + 127) / 128, GT>>>(0, 1, out_h, bias1);
    // 6: edge pass layer 2
    k_edge_pass<<<N_NODES / 4, 256>>>(1, ea, W1, b1);
    // 7: GEMM layer 2 -> out_h
    int sout2 = h_fits ? 2 : 0;
    k_gemm<<<(N_NODES + 127) / 128, GT>>>(1, sout2, out_h, bias2);

    // 8: edge embedding + log_softmax
    if (n_ee > 0 || n_lsm > 0)
        k_edge_embed<<<(N_EDGES + 255) / 256, 256>>>(ea, We, be, out_ee, out_lsm,
                                                     n_ee, n_lsm);
    // 9: edge_index passthrough
    if (n_ei > 0)
        k_ei_copy<<<(n_ei + 255) / 256, 256>>>(ei, out_ei, n_ei);
}

// round 8
// speedup vs baseline: 1.4468x; 1.4468x over previous
#include <cuda_runtime.h>
#include <math.h>

#define N_NODES 20000
#define N_EDGES 400000
#define KDIM 4160
typedef unsigned long long ull;

// ---------------- device globals --------------------------------------------
__device__ float g_S[(size_t)N_NODES * KDIM];    // per-node coefficient rows
__device__ float g_B[2][KDIM * 16];              // GEMM B per layer
__device__ float g_h0[N_NODES * 16];
__device__ float g_h1[N_NODES * 16];
__device__ int   g_deg[N_NODES];                 // re-zeroed by k_fill
__device__ int   g_cursor[N_NODES];              // re-zeroed by k_scan
__device__ int   g_off[N_NODES + 1];
__device__ int2  g_es[N_EDGES];                  // (edge id, src) sorted by dst

__device__ __forceinline__ float* pick_buf(int s, float* ext) {
    if (s == 0) return g_h0;
    if (s == 1) return g_h1;
    return ext;
}

// ---------------- f32x2 helpers ----------------------------------------------
__device__ __forceinline__ ull pack2(float a, float b) {
    ull r; asm("mov.b64 %0, {%1, %2};" : "=l"(r) : "f"(a), "f"(b)); return r;
}
__device__ __forceinline__ void unpack2(ull v, float& a, float& b) {
    asm("mov.b64 {%0, %1}, %2;" : "=f"(a), "=f"(b) : "l"(v));
}
__device__ __forceinline__ ull fma2(ull a, ull b, ull c) {
    ull d; asm("fma.rn.f32x2 %0, %1, %2, %3;" : "=l"(d) : "l"(a), "l"(b), "l"(c));
    return d;
}
__device__ __forceinline__ ull add2(ull a, ull b) {
    ull d; asm("add.rn.f32x2 %0, %1, %2;" : "=l"(d) : "l"(a), "l"(b)); return d;
}

// ---------------- launch 0: degree count + node embedding --------------------
#define COUNT_BLOCKS 1563
__global__ void k_count_embed(const int* __restrict__ ei,
                              const float* __restrict__ x,
                              const float* __restrict__ Wn,
                              const float* __restrict__ bn) {
    int b = blockIdx.x;
    if (b < COUNT_BLOCKS) {
        int e = b * 256 + threadIdx.x;
        if (e < N_EDGES) atomicAdd(&g_deg[ei[N_EDGES + e]], 1);
    } else {
        __shared__ float sW[256];
        __shared__ float sb[16];
        int tid = threadIdx.x;
        sW[tid] = Wn[tid];
        if (tid < 16) sb[tid] = bn[tid];
        __syncthreads();
        int n = (b - COUNT_BLOCKS) * 256 + tid;
        if (n >= N_NODES) return;
        float xi[16];
        const float4* xp = (const float4*)(x + (size_t)n * 16);
#pragma unroll
        for (int q = 0; q < 4; q++) {
            float4 v = xp[q];
            xi[4*q] = v.x; xi[4*q+1] = v.y; xi[4*q+2] = v.z; xi[4*q+3] = v.w;
        }
        float o[16];
#pragma unroll
        for (int d = 0; d < 16; d++) {
            float acc = sb[d];
#pragma unroll
            for (int k = 0; k < 16; k++) acc = fmaf(xi[k], sW[k*16+d], acc);
            o[d] = fmaxf(acc, 0.f);
        }
        float4* op = (float4*)(g_h0 + (size_t)n * 16);
#pragma unroll
        for (int q = 0; q < 4; q++)
            op[q] = make_float4(o[4*q], o[4*q+1], o[4*q+2], o[4*q+3]);
    }
}

// ---------------- launch 1: prefix scan --------------------------------------
__global__ void __launch_bounds__(1024) k_scan() {
    __shared__ int sm[1024];
    int t = threadIdx.x;
    int base = t * 20;
    int vals[20];
    int local = 0;
#pragma unroll
    for (int i = 0; i < 20; i++) {
        int idx = base + i;
        vals[i] = (idx < N_NODES) ? g_deg[idx] : 0;
        local += vals[i];
    }
    sm[t] = local;
    __syncthreads();
    for (int off = 1; off < 1024; off <<= 1) {
        int v = (t >= off) ? sm[t - off] : 0;
        __syncthreads();
        sm[t] += v;
        __syncthreads();
    }
    int run = sm[t] - local;
#pragma unroll
    for (int i = 0; i < 20; i++) {
        int idx = base + i;
        if (idx < N_NODES) { g_off[idx] = run; run += vals[i]; g_cursor[idx] = 0; }
    }
    if (t == 0) g_off[N_NODES] = N_EDGES;
}

// ---------------- launch 2: fill sorted edge list ----------------------------
__global__ void k_fill(const int* __restrict__ ei) {
    int e = blockIdx.x * blockDim.x + threadIdx.x;
    if (e < N_EDGES) {
        int d = ei[N_EDGES + e];
        int pos = g_off[d] + atomicAdd(&g_cursor[d], 1);
        g_es[pos] = make_int2(e, ei[e]);
    }
    if (e < N_NODES) g_deg[e] = 0;
}

// ---------------- edge pass: build S rows (4 warps per node) -----------------
__global__ void __launch_bounds__(256, 2) k_edge_pass(
    int sin, const float* __restrict__ ea,
    const float* __restrict__ W1, const float* __restrict__ b1) {
    const float* hin = (sin == 0) ? g_h0 : g_h1;
    int tid = threadIdx.x, wid = tid >> 5, l = tid & 31;
    int w = wid & 3;                     // k-quarter
    int n = blockIdx.x * 2 + (wid >> 2); // 2 nodes per block
    int k = w * 32 + l;

    ull w1r[8];
    float b1k = b1[k];
#pragma unroll
    for (int q = 0; q < 8; q++)
        w1r[q] = pack2(W1[(2*q)*128 + k], W1[(2*q+1)*128 + k]);

    int start = g_off[n], end = g_off[n + 1];
    ull T[8];
#pragma unroll
    for (int q = 0; q < 8; q++) T[q] = 0ull;
    ull Hs[8];
#pragma unroll
    for (int q = 0; q < 8; q++) Hs[q] = 0ull;
    float Hsum = 0.f;

    for (int pos = start; pos < end; pos++) {
        int2 es = g_es[pos];
        const ulonglong2* eap = (const ulonglong2*)(ea + (size_t)es.x * 16);
        const ulonglong2* hjp = (const ulonglong2*)(hin + (size_t)es.y * 16);
        ulonglong2 e0 = eap[0], e1 = eap[1], e2 = eap[2], e3 = eap[3];
        ulonglong2 h0 = hjp[0], h1 = hjp[1], h2 = hjp[2], h3 = hjp[3];
        ull ev[8] = {e0.x, e0.y, e1.x, e1.y, e2.x, e2.y, e3.x, e3.y};
        ull hv[8] = {h0.x, h0.y, h1.x, h1.y, h2.x, h2.y, h3.x, h3.y};
        if (w == 0) {
#pragma unroll
            for (int q = 0; q < 8; q++) Hs[q] = add2(Hs[q], hv[q]);
        }
        ull acc = pack2(b1k, 0.f);
#pragma unroll
        for (int q = 0; q < 8; q++) acc = fma2(ev[q], w1r[q], acc);
        float a0, a1; unpack2(acc, a0, a1);
        float hd = fmaxf(a0 + a1, 0.f);
        Hsum += hd;
        ull hd2 = pack2(hd, hd);
#pragma unroll
        for (int q = 0; q < 8; q++) T[q] = fma2(hd2, hv[q], T[q]);
    }

    float* Srow = g_S + (size_t)n * KDIM;

    // T rows: S[k*16 + j]
    {
        float t[16];
#pragma unroll
        for (int q = 0; q < 8; q++) unpack2(T[q], t[2*q], t[2*q+1]);
        float4* dT = (float4*)(Srow + (size_t)k * 16);
        dT[0] = make_float4(t[0], t[1], t[2], t[3]);
        dT[1] = make_float4(t[4], t[5], t[6], t[7]);
        dT[2] = make_float4(t[8], t[9], t[10], t[11]);
        dT[3] = make_float4(t[12], t[13], t[14], t[15]);
    }

    // Hsum ⊗ h rows: S[2048 + k*16 + r]
    float hn = (l < 16) ? hin[(size_t)n * 16 + l] : 0.f;
    {
        float u[16];
#pragma unroll
        for (int r = 0; r < 16; r++)
            u[r] = Hsum * __shfl_sync(0xffffffffu, hn, r);
        float4* dU = (float4*)(Srow + 2048 + (size_t)k * 16);
        dU[0] = make_float4(u[0], u[1], u[2], u[3]);
        dU[1] = make_float4(u[4], u[5], u[6], u[7]);
        dU[2] = make_float4(u[8], u[9], u[10], u[11]);
        dU[3] = make_float4(u[12], u[13], u[14], u[15]);
    }

    if (w == 0) {
        float dg = (float)(end - start);
        if (l < 16) {
            Srow[4096 + l] = dg * hn;     // pairs with b2 dst rows
            Srow[4128 + l] = hn;          // pairs with root rows
            Srow[4144 + l] = 0.f;         // pad (B rows are zero anyway)
        }
        if (l == 0) {
#pragma unroll
            for (int q = 0; q < 8; q++) {
                float a, b; unpack2(Hs[q], a, b);
                Srow[4112 + 2*q] = a;     // pairs with b2 src rows
                Srow[4112 + 2*q + 1] = b;
            }
        }
    }
}

// ---------------- build B (both layers) + seed outputs with bias -------------
#define NB_ELEM (2 * KDIM * 16)
__global__ void k_init(const float* __restrict__ W2, const float* __restrict__ b2,
                       const float* __restrict__ root1, const float* __restrict__ root2,
                       const float* __restrict__ bias1, const float* __restrict__ bias2,
                       int sout2, float* ext) {
    int idx = blockIdx.x * 256 + threadIdx.x;
    if (idx < NB_ELEM) {
        int layer = idx / (KDIM * 16);
        int m = idx % (KDIM * 16);
        int kj = m >> 4, d = m & 15;
        const float* root = layer ? root2 : root1;
        float v = 0.f;
        if (kj < 2048) {                       // T rows
            int k = kj >> 4, j = kj & 15;
            v = W2[(size_t)k * 512 + (16 + j) * 16 + d];
        } else if (kj < 4096) {                // Hsum*h rows
            int mm = kj - 2048;
            int k = mm >> 4, r = mm & 15;
            v = W2[(size_t)k * 512 + r * 16 + d];
        } else if (kj < 4112) {                // deg*h rows
            v = b2[(kj - 4096) * 16 + d];
        } else if (kj < 4128) {                // Hs rows
            v = b2[256 + (kj - 4112) * 16 + d];
        } else if (kj < 4144) {                // h rows
            v = root[(kj - 4128) * 16 + d];
        }
        g_B[layer][kj * 16 + d] = v;
    } else if (idx < NB_ELEM + N_NODES * 16) {
        int m = idx - NB_ELEM;
        g_h1[m] = bias1[m & 15];
    } else if (idx < NB_ELEM + 2 * N_NODES * 16) {
        int m = idx - NB_ELEM - N_NODES * 16;
        float* h2 = pick_buf(sout2, ext);
        h2[m] = bias2[m & 15];
    }
}

// ---------------- GEMM: hout += S @ B (4-way K-split, atomicAdd) -------------
#define GT 256
#define SA_P 129
__global__ void __launch_bounds__(GT) k_gemm(int layer, int sout, float* ext) {
    __shared__ __align__(16) float sA[64 * SA_P];
    __shared__ __align__(16) float sB[64 * 16];
    float* hout = pick_buf(sout, ext);
    const float* B = g_B[layer];
    int tid = threadIdx.x;
    int n0 = blockIdx.x * 128;
    int ks = blockIdx.y;
    int c0 = (ks == 0) ? 0 : 17 + (ks - 1) * 16;
    int nc = (ks == 0) ? 17 : 16;
    int nn = tid & 127, half = tid >> 7;
    ull acc[4] = {0ull, 0ull, 0ull, 0ull};

    for (int ci = 0; ci < nc; ci++) {
        int k0 = (c0 + ci) * 64;
        __syncthreads();
        ((float4*)sB)[tid] = ((const float4*)(B + (size_t)k0 * 16))[tid];
        for (int i = tid; i < 2048; i += GT) {
            int an = i >> 4, q = i & 15;
            float4 v = make_float4(0.f, 0.f, 0.f, 0.f);
            if (n0 + an < N_NODES)
                v = *(const float4*)(g_S + (size_t)(n0 + an) * KDIM + k0 + 4*q);
            sA[(4*q + 0) * SA_P + an] = v.x;
            sA[(4*q + 1) * SA_P + an] = v.y;
            sA[(4*q + 2) * SA_P + an] = v.z;
            sA[(4*q + 3) * SA_P + an] = v.w;
        }
        __syncthreads();
#pragma unroll 8
        for (int k = 0; k < 64; k++) {
            float a = sA[k * SA_P + nn];
            ull a2 = pack2(a, a);
            ulonglong2 b01 = *(const ulonglong2*)&sB[k * 16 + 8 * half];
            ulonglong2 b23 = *(const ulonglong2*)&sB[k * 16 + 8 * half + 4];
            acc[0] = fma2(a2, b01.x, acc[0]);
            acc[1] = fma2(a2, b01.y, acc[1]);
            acc[2] = fma2(a2, b23.x, acc[2]);
            acc[3] = fma2(a2, b23.y, acc[3]);
        }
    }

    int n = n0 + nn;
    if (n < N_NODES) {
        float o[8];
        unpack2(acc[0], o[0], o[1]);
        unpack2(acc[1], o[2], o[3]);
        unpack2(acc[2], o[4], o[5]);
        unpack2(acc[3], o[6], o[7]);
        float* dst = hout + (size_t)n * 16 + 8 * half;
#pragma unroll
        for (int j = 0; j < 8; j++) atomicAdd(dst + j, o[j]);
    }
}

// ---------------- edge embedding + log_softmax --------------------------------
__global__ void k_edge_embed(const float* __restrict__ ea,
                             const float* __restrict__ We,
                             const float* __restrict__ be,
                             float* __restrict__ ee_out,
                             float* __restrict__ lsm_out,
                             int n_ee, int n_lsm) {
    __shared__ float sW[256];
    __shared__ float sb[16];
    int tid = threadIdx.x;
    if (tid < 256) sW[tid] = We[tid];
    if (tid < 16) sb[tid] = be[tid];
    __syncthreads();
    int e = blockIdx.x * blockDim.x + tid;
    if (e >= N_EDGES) return;
    float xi[16];
    const float4* xp = (const float4*)(ea + (size_t)e * 16);
#pragma unroll
    for (int q = 0; q < 4; q++) {
        float4 v = xp[q];
        xi[4*q] = v.x; xi[4*q+1] = v.y; xi[4*q+2] = v.z; xi[4*q+3] = v.w;
    }
    float v[16];
    float m = -1e30f;
#pragma unroll
    for (int d = 0; d < 16; d++) {
        float acc = sb[d];
#pragma unroll
        for (int k = 0; k < 16; k++) acc = fmaf(xi[k], sW[k*16+d], acc);
        v[d] = fmaxf(acc, 0.f);
        m = fmaxf(m, v[d]);
    }
    float s = 0.f;
#pragma unroll
    for (int d = 0; d < 16; d++) s += expf(v[d] - m);
    float ls = m + logf(s);
    if (e < n_ee) {
        float4* eo = (float4*)(ee_out + (size_t)e * 16);
#pragma unroll
        for (int q = 0; q < 4; q++)
            eo[q] = make_float4(v[4*q], v[4*q+1], v[4*q+2], v[4*q+3]);
    }
    if (e < n_lsm) {
        float4* lo = (float4*)(lsm_out + (size_t)e * 16);
#pragma unroll
        for (int q = 0; q < 4; q++)
            lo[q] = make_float4(v[4*q] - ls, v[4*q+1] - ls, v[4*q+2] - ls, v[4*q+3] - ls);
    }
}

// ---------------- edge_index passthrough --------------------------------------
__global__ void k_ei_copy(const int* __restrict__ ei, float* __restrict__ out,
                          int n_vals) {
    int i = blockIdx.x * blockDim.x + threadIdx.x;
    if (i < n_vals) out[i] = (float)ei[i];
}

// ---------------- launch -------------------------------------------------------
extern "C" void kernel_launch(void* const* d_in, const int* in_sizes, int n_in,
                              void* d_out, int out_size) {
    const float* x     = (const float*)d_in[0];
    const int*   ei    = (const int*)d_in[1];
    const float* ea    = (const float*)d_in[2];
    const float* Wn    = (const float*)d_in[3];
    const float* bn    = (const float*)d_in[4];
    const float* We    = (const float*)d_in[5];
    const float* be    = (const float*)d_in[6];
    const float* W1    = (const float*)d_in[7];
    const float* b1    = (const float*)d_in[8];
    const float* W2    = (const float*)d_in[9];
    const float* b2    = (const float*)d_in[10];
    const float* root1 = (const float*)d_in[11];
    const float* bias1 = (const float*)d_in[12];
    const float* root2 = (const float*)d_in[13];
    const float* bias2 = (const float*)d_in[14];

    float* out = (float*)d_out;
    size_t cap = (size_t)out_size;

    size_t ei_slots = (cap == 13120000) ? 0 : 2ull * N_EDGES;
    size_t off_h   = 0;
    size_t off_ei  = off_h + (size_t)N_NODES * 16;
    size_t off_ee  = off_ei + ei_slots;
    size_t off_lsm = off_ee + (size_t)N_EDGES * 16;
    auto avail = [&](size_t off) -> size_t { return off < cap ? cap - off : 0; };

    float* out_h   = out + off_h;
    float* out_ei  = out + off_ei;
    float* out_ee  = out + off_ee;
    float* out_lsm = out + off_lsm;

    bool h_fits = avail(off_h) >= (size_t)N_NODES * 16;
    int  n_ei   = ei_slots ? (int)min((size_t)(2 * N_EDGES), avail(off_ei)) : 0;
    int  n_ee   = (int)min((size_t)N_EDGES, avail(off_ee) / 16);
    int  n_lsm  = (int)min((size_t)N_EDGES, avail(off_lsm) / 16);
    int  sout2  = h_fits ? 2 : 0;

    // 0: degree count + node embedding
    k_count_embed<<<COUNT_BLOCKS + 79, 256>>>(ei, x, Wn, bn);
    // 1: prefix scan (re-zeros g_cursor)
    k_scan<<<1, 1024>>>();
    // 2: dst-sorted edge list (re-zeros g_deg)
    k_fill<<<COUNT_BLOCKS, 256>>>(ei);

    // 3: edge pass layer 1 (profiled by ncu -s)
    k_edge_pass<<<N_NODES / 2, 256>>>(0, ea, W1, b1);
    // 4: build B + seed g_h1/out_h with biases
    k_init<<<(NB_ELEM + 2 * N_NODES * 16 + 255) / 256, 256>>>(
        W2, b2, root1, root2, bias1, bias2, sout2, out_h);
    // 5: GEMM layer 1 -> g_h1 (+= on top of bias1)
    dim3 g1((N_NODES + 127) / 128, 4);
    k_gemm<<<g1, GT>>>(0, 1, out_h);
    // 6: edge pass layer 2
    k_edge_pass<<<N_NODES / 2, 256>>>(1, ea, W1, b1);
    // 7: GEMM layer 2 -> out_h (+= on top of bias2)
    k_gemm<<<g1, GT>>>(1, sout2, out_h);

    // 8: edge embedding + log_softmax
    if (n_ee > 0 || n_lsm > 0)
        k_edge_embed<<<(N_EDGES + 255) / 256, 256>>>(ea, We, be, out_ee, out_lsm,
                                                     n_ee, n_lsm);
    // 9: edge_index passthrough
    if (n_ei > 0)
        k_ei_copy<<<(n_ei + 255) / 256, 256>>>(ei, out_ei, n_ei);
}